// round 8
// baseline (speedup 1.0000x reference)
#include <cuda_runtime.h>

// B=512 rows, L=16 labels, N=8192 values. Single kernel, 512 blocks (1 wave).
// loss = sum_l inv[l] * A_l,  inv[l] = 1/((np*nn)^2 * 256)
// A_l  = sum_{i pos, j neg} S[i,j]
// S[i,j] = 0.5*( sum|t| + 256 - 16*sx_i + 16*sx_j ),  t = 1 - x[i,c] + x[j,d]
// (relu(t) = (t+|t|)/2 exactly; sum t closed-form.)
// Each block: one j-tile (16 rows) x TWO i-tiles (32 rows), processed
// sequentially to keep register pressure at 4-blocks/SM residency.
// Per-label partials (no global-setup dependency) -> ticketed last block.

#define NROW 512
#define NL   16
#define TI   16
#define NBLK 512                 // 32 j-tiles x 16 i-tile-pairs -> single wave
#define ASP  257                 // padded stride, per-label scatter array
#define XJP  17                  // padded stride, transposed xj tile

__device__ float        g_inv[NL];
__device__ float        g_pl[NBLK * NL];
__device__ unsigned int g_cnt = 0;

// ---- packed f32x2 helpers -------------------------------------------------
__device__ __forceinline__ unsigned long long pk2(float lo, float hi) {
    unsigned long long r;
    asm("mov.b64 %0, {%1, %2};" : "=l"(r) : "f"(lo), "f"(hi));
    return r;
}
__device__ __forceinline__ unsigned long long addx2(unsigned long long a,
                                                    unsigned long long b) {
    unsigned long long r;
    asm("add.rn.f32x2 %0, %1, %2;" : "=l"(r) : "l"(a), "l"(b));
    return r;
}
__device__ __forceinline__ void unpk2(unsigned long long v, float& lo, float& hi) {
    asm("mov.b64 {%0, %1}, %2;" : "=f"(lo), "=f"(hi) : "l"(v));
}

__global__ void __launch_bounds__(256) k_all(const int* __restrict__ yt,
                                             const float* __restrict__ yp,
                                             float* __restrict__ out, int n_out) {
    __shared__ float    xi[2 * TI * NL];     // two i-tiles, row-major
    __shared__ float    xjT[NL * XJP];       // j-tile, transposed + padded
    __shared__ float    As[NL * ASP];        // per-label scatter [l][tid]
    __shared__ float    A2[NL * 17];         // stage-2 partials [l][chunk]
    __shared__ float    wfin[NL];
    __shared__ unsigned pmI[2 * TI], nmJ[TI];
    __shared__ float    sxI[2 * TI], sxJ[TI];
    __shared__ int      cnt_s[NL];
    __shared__ int      is_last;

    const int b   = blockIdx.x;
    const int bj  = b & 31;          // j-tile (0..31)
    const int bp  = b >> 5;          // i-tile pair (0..15): rows bp*32..bp*32+31
    const int tid = threadIdx.x;

    // ---- stage tiles ---------------------------------------------------------
    xi[tid]       = yp[bp * 512 + tid];
    xi[tid + 256] = yp[bp * 512 + 256 + tid];
    xjT[(tid & 15) * XJP + (tid >> 4)] = yp[bj * 256 + tid];   // transposed

    // ---- block 0: per-label n_pos -> g_inv ------------------------------------
    if (b == 0) {
        if (tid < NL) cnt_s[tid] = 0;
        __syncthreads();
        const int r0 = 2 * tid;
        unsigned m0 = 0, m1 = 0;
        const int4* y4 = (const int4*)(yt + r0 * NL);
        #pragma unroll
        for (int q = 0; q < 4; q++) {
            int4 v = y4[q];
            if (v.x) m0 |= 1u << (4 * q + 0);
            if (v.y) m0 |= 1u << (4 * q + 1);
            if (v.z) m0 |= 1u << (4 * q + 2);
            if (v.w) m0 |= 1u << (4 * q + 3);
        }
        #pragma unroll
        for (int q = 0; q < 4; q++) {
            int4 v = y4[4 + q];
            if (v.x) m1 |= 1u << (4 * q + 0);
            if (v.y) m1 |= 1u << (4 * q + 1);
            if (v.z) m1 |= 1u << (4 * q + 2);
            if (v.w) m1 |= 1u << (4 * q + 3);
        }
        #pragma unroll
        for (int l = 0; l < NL; l++) {
            unsigned b0 = __ballot_sync(0xffffffffu, (m0 >> l) & 1u);
            unsigned b1 = __ballot_sync(0xffffffffu, (m1 >> l) & 1u);
            if ((tid & 31) == 0) atomicAdd(&cnt_s[l], __popc(b0) + __popc(b1));
        }
        __syncthreads();
        if (tid < NL) {
            int np = cnt_s[tid], nn = NROW - np;
            float d = (float)np * (float)nn;           // <= 2^18, exact in fp32
            g_inv[tid] = (np > 0 && nn > 0) ? 1.0f / (d * d * 256.0f) : 0.0f;
        }
    }

    // ---- row masks: 32 i-rows + 16 j-rows --------------------------------------
    if (tid < 3 * TI) {
        int row = (tid < 2 * TI) ? (bp * 32 + tid) : (bj * TI + (tid - 2 * TI));
        unsigned m = 0;
        const int4* y4 = (const int4*)(yt + row * NL);
        #pragma unroll
        for (int q = 0; q < 4; q++) {
            int4 v = y4[q];
            if (v.x) m |= 1u << (4 * q + 0);
            if (v.y) m |= 1u << (4 * q + 1);
            if (v.z) m |= 1u << (4 * q + 2);
            if (v.w) m |= 1u << (4 * q + 3);
        }
        if (tid < 2 * TI) pmI[tid] = m;
        else              nmJ[tid - 2 * TI] = (~m) & 0xFFFFu;
    }
    __syncthreads();

    // ---- per-row sums (from staged tiles) ---------------------------------------
    if (tid < 2 * TI) {
        float s = 0.0f;
        #pragma unroll
        for (int c = 0; c < NL; c++) s += xi[tid * NL + c];
        sxI[tid] = s;
    } else if (tid < 3 * TI) {
        int j = tid - 2 * TI;
        float s = 0.0f;
        #pragma unroll
        for (int c = 0; c < NL; c++) s += xjT[c * XJP + j];
        sxJ[j] = s;
    }
    __syncthreads();

    // ---- hot loop: two i-tiles sequentially --------------------------------------
    const int il = tid >> 4;
    const int jl = tid & 15;
    const unsigned long long ABSM = 0x7FFFFFFF7FFFFFFFULL;

    float S0, S1;
    #pragma unroll
    for (int t = 0; t < 2; t++) {
        const float* xr = &xi[t * 256 + il * NL];
        unsigned long long ci2[8];
        #pragma unroll
        for (int k = 0; k < 8; k++)
            ci2[k] = pk2(1.0f - xr[2 * k], 1.0f - xr[2 * k + 1]);

        unsigned long long sa0 = 0, sa1 = 0;
        #pragma unroll
        for (int d = 0; d < NL; d++) {
            float xq = xjT[d * XJP + jl];          // conflict-free broadcast
            unsigned long long xq2 = pk2(xq, xq);
            #pragma unroll
            for (int k = 0; k < 8; k += 2) {
                unsigned long long t0 = addx2(ci2[k],     xq2) & ABSM;
                unsigned long long t1 = addx2(ci2[k + 1], xq2) & ABSM;
                sa0 = addx2(sa0, t0);
                sa1 = addx2(sa1, t1);
            }
        }
        float a0, a1, c0, c1;
        unpk2(sa0, a0, a1);
        unpk2(sa1, c0, c1);
        float s_abs = (a0 + a1) + (c0 + c1);
        float S = 0.5f * (s_abs + (256.0f - 16.0f * sxI[t * TI + il] + 16.0f * sxJ[jl]));
        if (t == 0) S0 = S; else S1 = S;
    }

    // ---- per-label scatter (both tiles fused) + block reduction -------------------
    unsigned mask0 = pmI[il]      & nmJ[jl];
    unsigned mask1 = pmI[16 + il] & nmJ[jl];
    #pragma unroll
    for (int l = 0; l < NL; l++) {
        float v = (((mask0 >> l) & 1u) ? S0 : 0.0f)
                + (((mask1 >> l) & 1u) ? S1 : 0.0f);
        As[l * ASP + tid] = v;
    }
    __syncthreads();

    {
        const int l = tid & 15, ch = tid >> 4;
        float a = 0.0f;
        #pragma unroll
        for (int k = 0; k < 16; k++) a += As[l * ASP + ch * 16 + k];
        A2[l * 17 + ch] = a;
    }
    __syncthreads();

    if (tid < NL) {
        float s = 0.0f;
        #pragma unroll
        for (int c = 0; c < 16; c++) s += A2[tid * 17 + c];
        g_pl[b * NL + tid] = s;
        __threadfence();               // publish partials (and g_inv for b==0)
    }
    __syncthreads();

    if (tid == 0) {
        unsigned t = atomicAdd(&g_cnt, 1u);
        is_last = (t == NBLK - 1);
    }
    __syncthreads();

    // ---- last block: global per-label reduce + weighted combine --------------------
    if (is_last) {
        __threadfence();
        const int l = tid & 15, ch = tid >> 4;
        float a = 0.0f;
        for (int k = 0; k < 32; k++)                    // fixed order: deterministic
            a += g_pl[(ch * 32 + k) * NL + l];
        A2[l * 17 + ch] = a;
        __syncthreads();
        if (tid < NL) {
            float s = 0.0f;
            #pragma unroll
            for (int c = 0; c < 16; c++) s += A2[tid * 17 + c];
            wfin[tid] = s * g_inv[tid];
        }
        __syncthreads();
        if (tid == 0) {
            float loss = 0.0f;
            #pragma unroll
            for (int l2 = 0; l2 < NL; l2++) loss += wfin[l2];
            out[0] = loss;
            g_cnt  = 0;                 // reset for next graph replay
        }
        for (int i = tid + 1; i < n_out; i += 256) out[i] = 0.0f;
    }
}

extern "C" void kernel_launch(void* const* d_in, const int* in_sizes, int n_in,
                              void* d_out, int out_size) {
    const int*   yt  = (const int*)d_in[0];    // y_true int32 [512*16]
    const float* yp  = (const float*)d_in[1];  // y_pred fp32  [512*16]
    float*       out = (float*)d_out;

    k_all<<<NBLK, 256>>>(yt, yp, out, out_size);
}

// round 9
// speedup vs baseline: 1.1552x; 1.1552x over previous
#include <cuda_runtime.h>

// B=512 rows, L=16 labels, N=8192 values. Single kernel, 1024 blocks.
// loss = sum_l inv[l] * A_l,  inv[l] = 1/((np*nn)^2 * 256)
// A_l  = sum_{i pos, j neg} S[i,j]
// S[i,j] = 0.5*( sum|t| + 256 - 16*sx_i + 16*sx_j ),  t = 1 - x[i,c] + x[j,d]
// Per-label block partials accumulated into g_acc[16] as 2^26 fixed-point
// integers (deterministic, order-independent); ticketed last block combines.

#define NROW 512
#define NL   16
#define TI   16
#define GB   32
#define NBLK 1024
#define ASP  257                 // padded stride, per-label scatter array
#define XP   20                  // padded row stride (floats), 80B = 16B-aligned
#define FPSCALE    67108864.0f   // 2^26
#define FPSCALE_I  (1.0f / 67108864.0f)

__device__ float              g_inv[NL];
__device__ unsigned long long g_acc[NL];     // zero-initialized at load
__device__ unsigned int       g_cnt = 0;

// ---- packed f32x2 helpers -------------------------------------------------
__device__ __forceinline__ unsigned long long pk2(float lo, float hi) {
    unsigned long long r;
    asm("mov.b64 %0, {%1, %2};" : "=l"(r) : "f"(lo), "f"(hi));
    return r;
}
__device__ __forceinline__ unsigned long long addx2(unsigned long long a,
                                                    unsigned long long b) {
    unsigned long long r;
    asm("add.rn.f32x2 %0, %1, %2;" : "=l"(r) : "l"(a), "l"(b));
    return r;
}
__device__ __forceinline__ void unpk2(unsigned long long v, float& lo, float& hi) {
    asm("mov.b64 {%0, %1}, %2;" : "=f"(lo), "=f"(hi) : "l"(v));
}

__global__ void __launch_bounds__(256, 5) k_all(const int* __restrict__ yt,
                                                const float* __restrict__ yp,
                                                float* __restrict__ out, int n_out) {
    __shared__ __align__(16) float xi[TI * XP];   // i-tile, padded rows
    __shared__ __align__(16) float xj[TI * XP];   // j-tile, padded rows
    __shared__ float    As[NL * ASP];             // per-label scatter [l][tid]
    __shared__ float    A2[NL * 17];              // stage-2 partials [l][chunk]
    __shared__ float    wfin[NL];
    __shared__ unsigned pmI[TI], nmJ[TI];
    __shared__ float    sxI[TI], sxJ[TI];
    __shared__ int      cnt_s[NL];
    __shared__ int      is_last;

    const int b   = blockIdx.x;
    const int bi  = b & (GB - 1);
    const int bj  = b >> 5;
    const int tid = threadIdx.x;

    // ---- stage tiles into padded layout --------------------------------------
    {
        int r = tid >> 4, c = tid & 15;
        xi[r * XP + c] = yp[bi * 256 + tid];
        xj[r * XP + c] = yp[bj * 256 + tid];
    }

    // ---- block 0: per-label n_pos -> g_inv ------------------------------------
    if (b == 0) {
        if (tid < NL) cnt_s[tid] = 0;
        __syncthreads();
        const int r0 = 2 * tid;
        unsigned m0 = 0, m1 = 0;
        const int4* y4 = (const int4*)(yt + r0 * NL);
        #pragma unroll
        for (int q = 0; q < 4; q++) {
            int4 v = y4[q];
            if (v.x) m0 |= 1u << (4 * q + 0);
            if (v.y) m0 |= 1u << (4 * q + 1);
            if (v.z) m0 |= 1u << (4 * q + 2);
            if (v.w) m0 |= 1u << (4 * q + 3);
        }
        #pragma unroll
        for (int q = 0; q < 4; q++) {
            int4 v = y4[4 + q];
            if (v.x) m1 |= 1u << (4 * q + 0);
            if (v.y) m1 |= 1u << (4 * q + 1);
            if (v.z) m1 |= 1u << (4 * q + 2);
            if (v.w) m1 |= 1u << (4 * q + 3);
        }
        #pragma unroll
        for (int l = 0; l < NL; l++) {
            unsigned b0 = __ballot_sync(0xffffffffu, (m0 >> l) & 1u);
            unsigned b1 = __ballot_sync(0xffffffffu, (m1 >> l) & 1u);
            if ((tid & 31) == 0) atomicAdd(&cnt_s[l], __popc(b0) + __popc(b1));
        }
        __syncthreads();
        if (tid < NL) {
            int np = cnt_s[tid], nn = NROW - np;
            float d = (float)np * (float)nn;           // <= 2^18, exact in fp32
            g_inv[tid] = (np > 0 && nn > 0) ? 1.0f / (d * d * 256.0f) : 0.0f;
            // fenced later by the same threads (0..15) in the epilogue
        }
    }

    // ---- row masks: 16 i-rows + 16 j-rows --------------------------------------
    if (tid < 2 * TI) {
        int row = (tid < TI) ? (bi * TI + tid) : (bj * TI + (tid - TI));
        unsigned m = 0;
        const int4* y4 = (const int4*)(yt + row * NL);
        #pragma unroll
        for (int q = 0; q < 4; q++) {
            int4 v = y4[q];
            if (v.x) m |= 1u << (4 * q + 0);
            if (v.y) m |= 1u << (4 * q + 1);
            if (v.z) m |= 1u << (4 * q + 2);
            if (v.w) m |= 1u << (4 * q + 3);
        }
        if (tid < TI) pmI[tid] = m;
        else          nmJ[tid - TI] = (~m) & 0xFFFFu;
    }
    __syncthreads();

    // ---- per-row sums (vectorized from staged tiles) ----------------------------
    if (tid < TI) {
        const float4* p = (const float4*)&xi[tid * XP];
        float4 a = p[0], c4 = p[1], d4 = p[2], e4 = p[3];
        sxI[tid] = ((a.x + a.y) + (a.z + a.w)) + ((c4.x + c4.y) + (c4.z + c4.w))
                 + ((d4.x + d4.y) + (d4.z + d4.w)) + ((e4.x + e4.y) + (e4.z + e4.w));
    } else if (tid < 2 * TI) {
        int j = tid - TI;
        const float4* p = (const float4*)&xj[j * XP];
        float4 a = p[0], c4 = p[1], d4 = p[2], e4 = p[3];
        sxJ[j] = ((a.x + a.y) + (a.z + a.w)) + ((c4.x + c4.y) + (c4.z + c4.w))
               + ((d4.x + d4.y) + (d4.z + d4.w)) + ((e4.x + e4.y) + (e4.z + e4.w));
    }
    __syncthreads();

    // ---- hot loop ----------------------------------------------------------------
    const int il = tid >> 4;
    const int jl = tid & 15;
    const unsigned long long ABSM = 0x7FFFFFFF7FFFFFFFULL;

    unsigned long long ci2[8];
    {
        const float4* xr = (const float4*)&xi[il * XP];
        float4 a = xr[0], c4 = xr[1], d4 = xr[2], e4 = xr[3];
        ci2[0] = pk2(1.0f - a.x,  1.0f - a.y);
        ci2[1] = pk2(1.0f - a.z,  1.0f - a.w);
        ci2[2] = pk2(1.0f - c4.x, 1.0f - c4.y);
        ci2[3] = pk2(1.0f - c4.z, 1.0f - c4.w);
        ci2[4] = pk2(1.0f - d4.x, 1.0f - d4.y);
        ci2[5] = pk2(1.0f - d4.z, 1.0f - d4.w);
        ci2[6] = pk2(1.0f - e4.x, 1.0f - e4.y);
        ci2[7] = pk2(1.0f - e4.z, 1.0f - e4.w);
    }

    unsigned long long sa0 = 0, sa1 = 0;
    const float4* qr = (const float4*)&xj[jl * XP];
    #pragma unroll
    for (int dc = 0; dc < 4; dc++) {
        float4 q = qr[dc];                 // 4 xq values per LDS.128
        float qq[4] = {q.x, q.y, q.z, q.w};
        #pragma unroll
        for (int di = 0; di < 4; di++) {
            unsigned long long xq2 = pk2(qq[di], qq[di]);
            #pragma unroll
            for (int k = 0; k < 8; k += 2) {
                unsigned long long t0 = addx2(ci2[k],     xq2) & ABSM;
                unsigned long long t1 = addx2(ci2[k + 1], xq2) & ABSM;
                sa0 = addx2(sa0, t0);
                sa1 = addx2(sa1, t1);
            }
        }
    }

    float a0, a1, c0, c1;
    unpk2(sa0, a0, a1);
    unpk2(sa1, c0, c1);
    float s_abs = (a0 + a1) + (c0 + c1);
    float S = 0.5f * (s_abs + (256.0f - 16.0f * sxI[il] + 16.0f * sxJ[jl]));

    // ---- per-label scatter + block reduction ---------------------------------------
    unsigned mask = pmI[il] & nmJ[jl];
    #pragma unroll
    for (int l = 0; l < NL; l++)
        As[l * ASP + tid] = ((mask >> l) & 1u) ? S : 0.0f;
    __syncthreads();

    {
        const int l = tid & 15, ch = tid >> 4;
        float a = 0.0f;
        #pragma unroll
        for (int k = 0; k < 16; k++) a += As[l * ASP + ch * 16 + k];
        A2[l * 17 + ch] = a;
    }
    __syncthreads();

    if (tid < NL) {
        float s = 0.0f;
        #pragma unroll
        for (int c = 0; c < 16; c++) s += A2[tid * 17 + c];
        // deterministic fixed-point accumulation (A_l >= 0 always)
        atomicAdd(&g_acc[tid], (unsigned long long)__float2ll_rn(s * FPSCALE));
        __threadfence();           // also covers block 0's earlier g_inv writes
    }
    __syncthreads();

    if (tid == 0) {
        unsigned t = atomicAdd(&g_cnt, 1u);
        is_last = (t == NBLK - 1);
    }
    __syncthreads();

    // ---- last block: tiny tail -------------------------------------------------------
    if (is_last) {
        __threadfence();
        if (tid < NL) {
            long long v = (long long)g_acc[tid];
            wfin[tid] = (float)v * FPSCALE_I * g_inv[tid];
            g_acc[tid] = 0ULL;      // reset for next graph replay
        }
        __syncthreads();
        if (tid == 0) {
            float loss = 0.0f;
            #pragma unroll
            for (int l2 = 0; l2 < NL; l2++) loss += wfin[l2];
            out[0] = loss;
            g_cnt  = 0;             // reset for next graph replay
        }
        for (int i = tid + 1; i < n_out; i += 256) out[i] = 0.0f;
    }
}

extern "C" void kernel_launch(void* const* d_in, const int* in_sizes, int n_in,
                              void* d_out, int out_size) {
    const int*   yt  = (const int*)d_in[0];    // y_true int32 [512*16]
    const float* yp  = (const float*)d_in[1];  // y_pred fp32  [512*16]
    float*       out = (float*)d_out;

    k_all<<<NBLK, 256>>>(yt, yp, out, out_size);
}

// round 10
// speedup vs baseline: 1.3400x; 1.1600x over previous
#include <cuda_runtime.h>
#include <cuda_fp16.h>

// B=512 rows, L=16 labels, N=8192 values. Single kernel, 1024 blocks.
// loss = sum_l inv[l] * A_l,  inv[l] = 1/((np*nn)^2 * 256)
// A_l  = sum_{i pos, j neg} S[i,j],  S[i,j] = sum_{c,d} relu(1 - x[i,c] + x[j,d])
// Hot loop in packed fp16: t = hadd2(a2, x2); relu = hmax2(t,0); acc += relu.
// Per-label block partials accumulated into g_acc[16] as 2^26 fixed-point
// integers (deterministic, order-independent); ticketed last block combines.

#define NROW 512
#define NL   16
#define TI   16
#define GB   32
#define NBLK 1024
#define ASP  257                 // padded stride, per-label scatter array
#define XP   20                  // padded row stride (floats) for xi tile
#define FPSCALE    67108864.0f   // 2^26
#define FPSCALE_I  (1.0f / 67108864.0f)

__device__ float              g_inv[NL];
__device__ unsigned long long g_acc[NL];     // zero-initialized at load
__device__ unsigned int       g_cnt = 0;

__global__ void __launch_bounds__(256, 6) k_all(const int* __restrict__ yt,
                                                const float* __restrict__ yp,
                                                float* __restrict__ out, int n_out) {
    __shared__ __align__(16) float   xi[TI * XP];      // i-tile fp32, padded rows
    __shared__ __align__(16) __half2 xjh2[TI * TI];    // j-tile, splatted half2 [row][d]
    __shared__ float    As[NL * ASP];                  // per-label scatter [l][tid]
    __shared__ float    A2[NL * 17];                   // stage-2 partials [l][chunk]
    __shared__ float    wfin[NL];
    __shared__ unsigned pmI[TI], nmJ[TI];
    __shared__ int      cnt_s[NL];
    __shared__ int      is_last;

    const int b   = blockIdx.x;
    const int bi  = b & (GB - 1);
    const int bj  = b >> 5;
    const int tid = threadIdx.x;

    // ---- stage tiles ------------------------------------------------------------
    {
        int r = tid >> 4, c = tid & 15;
        xi[r * XP + c] = yp[bi * 256 + tid];
        // j value splatted into both halves: xjh2[row][d] = (h, h)
        xjh2[r * TI + c] = __float2half2_rn(yp[bj * 256 + r * TI + c]);
    }

    // ---- block 0: per-label n_pos -> g_inv ----------------------------------------
    if (b == 0) {
        if (tid < NL) cnt_s[tid] = 0;
        __syncthreads();
        const int r0 = 2 * tid;
        unsigned m0 = 0, m1 = 0;
        const int4* y4 = (const int4*)(yt + r0 * NL);
        #pragma unroll
        for (int q = 0; q < 4; q++) {
            int4 v = y4[q];
            if (v.x) m0 |= 1u << (4 * q + 0);
            if (v.y) m0 |= 1u << (4 * q + 1);
            if (v.z) m0 |= 1u << (4 * q + 2);
            if (v.w) m0 |= 1u << (4 * q + 3);
        }
        #pragma unroll
        for (int q = 0; q < 4; q++) {
            int4 v = y4[4 + q];
            if (v.x) m1 |= 1u << (4 * q + 0);
            if (v.y) m1 |= 1u << (4 * q + 1);
            if (v.z) m1 |= 1u << (4 * q + 2);
            if (v.w) m1 |= 1u << (4 * q + 3);
        }
        #pragma unroll
        for (int l = 0; l < NL; l++) {
            unsigned b0 = __ballot_sync(0xffffffffu, (m0 >> l) & 1u);
            unsigned b1 = __ballot_sync(0xffffffffu, (m1 >> l) & 1u);
            if ((tid & 31) == 0) atomicAdd(&cnt_s[l], __popc(b0) + __popc(b1));
        }
        __syncthreads();
        if (tid < NL) {
            int np = cnt_s[tid], nn = NROW - np;
            float d = (float)np * (float)nn;            // <= 2^18, exact in fp32
            g_inv[tid] = (np > 0 && nn > 0) ? 1.0f / (d * d * 256.0f) : 0.0f;
            // fenced below by the same threads' __threadfence in the epilogue
        }
    }

    // ---- row masks: 16 i-rows + 16 j-rows -------------------------------------------
    if (tid < 2 * TI) {
        int row = (tid < TI) ? (bi * TI + tid) : (bj * TI + (tid - TI));
        unsigned m = 0;
        const int4* y4 = (const int4*)(yt + row * NL);
        #pragma unroll
        for (int q = 0; q < 4; q++) {
            int4 v = y4[q];
            if (v.x) m |= 1u << (4 * q + 0);
            if (v.y) m |= 1u << (4 * q + 1);
            if (v.z) m |= 1u << (4 * q + 2);
            if (v.w) m |= 1u << (4 * q + 3);
        }
        if (tid < TI) pmI[tid] = m;
        else          nmJ[tid - TI] = (~m) & 0xFFFFu;
    }
    __syncthreads();

    // ---- hot loop --------------------------------------------------------------------
    const int il = tid >> 4;
    const int jl = tid & 15;

    // a_c = 1 - x[i,c], packed as 8 half2
    __half2 ah[8];
    {
        const float4* xr = (const float4*)&xi[il * XP];
        float4 a = xr[0], c4 = xr[1], d4 = xr[2], e4 = xr[3];
        ah[0] = __floats2half2_rn(1.0f - a.x,  1.0f - a.y);
        ah[1] = __floats2half2_rn(1.0f - a.z,  1.0f - a.w);
        ah[2] = __floats2half2_rn(1.0f - c4.x, 1.0f - c4.y);
        ah[3] = __floats2half2_rn(1.0f - c4.z, 1.0f - c4.w);
        ah[4] = __floats2half2_rn(1.0f - d4.x, 1.0f - d4.y);
        ah[5] = __floats2half2_rn(1.0f - d4.z, 1.0f - d4.w);
        ah[6] = __floats2half2_rn(1.0f - e4.x, 1.0f - e4.y);
        ah[7] = __floats2half2_rn(1.0f - e4.z, 1.0f - e4.w);
    }

    const __half2 hz = __float2half2_rn(0.0f);
    __half2 acc[8];
    #pragma unroll
    for (int k = 0; k < 8; k++) acc[k] = hz;

    const uint4* qp = (const uint4*)&xjh2[jl * TI];   // 16 half2 = 4x uint4
    #pragma unroll
    for (int dc = 0; dc < 4; dc++) {
        uint4 qv = qp[dc];                             // 4 splatted half2 (4 d's)
        unsigned qw[4] = {qv.x, qv.y, qv.z, qv.w};
        #pragma unroll
        for (int di = 0; di < 4; di++) {
            __half2 xq = *reinterpret_cast<__half2*>(&qw[di]);
            #pragma unroll
            for (int k = 0; k < 8; k++) {
                __half2 t = __hadd2(ah[k], xq);
                acc[k] = __hadd2(acc[k], __hmax2(t, hz));
            }
        }
    }

    float S = 0.0f;
    #pragma unroll
    for (int k = 0; k < 8; k++) {
        float2 f = __half22float2(acc[k]);
        S += f.x + f.y;
    }

    // ---- per-label scatter + block reduction -------------------------------------------
    unsigned mask = pmI[il] & nmJ[jl];
    #pragma unroll
    for (int l = 0; l < NL; l++)
        As[l * ASP + tid] = ((mask >> l) & 1u) ? S : 0.0f;
    __syncthreads();

    {
        const int l = tid & 15, ch = tid >> 4;
        float a = 0.0f;
        #pragma unroll
        for (int k = 0; k < 16; k++) a += As[l * ASP + ch * 16 + k];
        A2[l * 17 + ch] = a;
    }
    __syncthreads();

    if (tid < NL) {
        float s = 0.0f;
        #pragma unroll
        for (int c = 0; c < 16; c++) s += A2[tid * 17 + c];
        // deterministic fixed-point accumulation (A_l >= 0 always)
        atomicAdd(&g_acc[tid], (unsigned long long)__float2ll_rn(s * FPSCALE));
        __threadfence();            // also publishes block 0's g_inv writes
    }
    __syncthreads();

    if (tid == 0) {
        unsigned t = atomicAdd(&g_cnt, 1u);
        is_last = (t == NBLK - 1);
    }
    __syncthreads();

    // ---- last block: tiny tail ------------------------------------------------------------
    if (is_last) {
        __threadfence();
        if (tid < NL) {
            long long v = (long long)g_acc[tid];
            wfin[tid] = (float)v * FPSCALE_I * g_inv[tid];
            g_acc[tid] = 0ULL;      // reset for next graph replay
        }
        __syncthreads();
        if (tid == 0) {
            float loss = 0.0f;
            #pragma unroll
            for (int l2 = 0; l2 < NL; l2++) loss += wfin[l2];
            out[0] = loss;
            g_cnt  = 0;             // reset for next graph replay
        }
        for (int i = tid + 1; i < n_out; i += 256) out[i] = 0.0f;
    }
}

extern "C" void kernel_launch(void* const* d_in, const int* in_sizes, int n_in,
                              void* d_out, int out_size) {
    const int*   yt  = (const int*)d_in[0];    // y_true int32 [512*16]
    const float* yp  = (const float*)d_in[1];  // y_pred fp32  [512*16]
    float*       out = (float*)d_out;

    k_all<<<NBLK, 256>>>(yt, yp, out, out_size);
}